// round 5
// baseline (speedup 1.0000x reference)
#include <cuda_runtime.h>
#include <math.h>

// ---------------------------------------------------------------------------
// Problem constants
// ---------------------------------------------------------------------------
#define Bb   2
#define Ss   1024
#define Tt   128
#define Dd   1024
#define Hh   16
#define HDd  64
#define Ll   6
#define Cc   129            // 1 + T conditioning tokens
#define NT   (Bb*Ss)        // 2048 flattened audio tokens

// ---------------------------------------------------------------------------
// Scratch (device globals; allocation-free per harness rules)
// ---------------------------------------------------------------------------
__device__ float g_x   [NT*Dd];
__device__ float g_h   [NT*Dd];
__device__ float g_qkv [NT*3*Dd];
__device__ float g_o   [NT*Dd];
__device__ float g_q   [NT*Dd];
__device__ float g_f   [NT*4*Dd];
__device__ float g_cond[Bb*Cc*Dd];
__device__ float g_ckv [Bb*Cc*2*Dd];
__device__ float g_spk [Bb*Dd];

__device__ __forceinline__ float gelu_f(float x) {
    return 0.5f * x * (1.0f + erff(x * 0.70710678118654752f));
}

__device__ __forceinline__ unsigned tf32u(float x) {
    unsigned u;
    asm("cvt.rna.tf32.f32 %0, %1;" : "=r"(u) : "f"(x));
    return u;
}

__device__ __forceinline__ void mma_tf32(float* c, const unsigned* a, const unsigned* b) {
    asm volatile(
        "mma.sync.aligned.m16n8k8.row.col.f32.tf32.tf32.f32 "
        "{%0,%1,%2,%3}, {%4,%5,%6,%7}, {%8,%9}, {%0,%1,%2,%3};"
        : "+f"(c[0]), "+f"(c[1]), "+f"(c[2]), "+f"(c[3])
        : "r"(a[0]), "r"(a[1]), "r"(a[2]), "r"(a[3]),
          "r"(b[0]), "r"(b[1]));
}

// ---------------------------------------------------------------------------
// TF32 tensor-core GEMM with cp.async 2-stage pipeline.
// C[M,N] = A[M,K] @ B[K,N]  (+bias, +gelu, +residual)
// 128x128 block tile, BK=16, 256 threads (8 warps, 32x64 warp tiles).
// flags: 1 = add bias (len N), 2 = gelu, 4 = add residual R[M,N]
// N % 128 == 0, K % 16 == 0. M arbitrary (guarded via zfill cp.async).
// Smem pads conflict-free for fragment reads:
//   As stride 20 -> row-bank offsets {r*20 mod 32} bijective over 8 rows
//   Bs stride 136 -> bank = (k*8 + n) & 31 bijective over 32 lanes
// Both strides are 16B-aligned (80B, 544B) as required by LDGSTS.
// ---------------------------------------------------------------------------
#define GBM 128
#define GBN 128
#define GBK 16
#define ASTR 20
#define BSTR 136
#define AELEM (GBM * ASTR)     // floats per A stage
#define BELEM (GBK * BSTR)     // floats per B stage

__global__ __launch_bounds__(256, 2) void gemm_tc(
    const float* __restrict__ A, const float* __restrict__ Bm,
    const float* __restrict__ bias, const float* __restrict__ R,
    float* __restrict__ C, int M, int N, int K, int flags)
{
    __shared__ float As[2 * AELEM];
    __shared__ float Bs[2 * BELEM];

    const int tid  = threadIdx.x;
    const int lane = tid & 31;
    const int wid  = tid >> 5;
    const int wm   = (wid >> 1) * 32;   // 4 warps along M
    const int wn   = (wid & 1) * 64;    // 2 warps along N
    const int bm   = blockIdx.y * GBM;
    const int bn   = blockIdx.x * GBN;
    const int lr   = lane >> 2;
    const int lc   = lane & 3;

    const unsigned as_u = (unsigned)__cvta_generic_to_shared(As);
    const unsigned bs_u = (unsigned)__cvta_generic_to_shared(Bs);

    float acc[2][8][4];
#pragma unroll
    for (int i = 0; i < 2; i++)
#pragma unroll
        for (int j = 0; j < 8; j++)
#pragma unroll
            for (int r = 0; r < 4; r++) acc[i][j][r] = 0.0f;

    // per-thread staging coordinates
    const int a_r  = tid >> 2;            // 0..63  (+64 for j=1)
    const int a_k  = (tid & 3) * 4;       // 0,4,8,12
    const int b_kr = tid >> 5;            // 0..7   (+8 for j=1)
    const int b_nn = (tid & 31) * 4;      // 0..124

    const int ntiles = K / GBK;

    // ---- prefetch helper (issues 4 LDGSTS.16B, no commit) ----
    auto stage = [&](int t, int buf) {
        const int k0 = t * GBK;
#pragma unroll
        for (int j = 0; j < 2; j++) {
            const int r   = a_r + 64 * j;
            const int row = bm + r;
            const int sz  = (row < M) ? 16 : 0;
            const float* src = A + (size_t)(row < M ? row : 0) * K + k0 + a_k;
            const unsigned dst = as_u + (unsigned)((buf * AELEM + r * ASTR + a_k) * 4);
            asm volatile("cp.async.cg.shared.global [%0], [%1], 16, %2;"
                         :: "r"(dst), "l"(src), "r"(sz));
        }
#pragma unroll
        for (int j = 0; j < 2; j++) {
            const int kr = b_kr + 8 * j;
            const float* src = Bm + (size_t)(k0 + kr) * N + bn + b_nn;
            const unsigned dst = bs_u + (unsigned)((buf * BELEM + kr * BSTR + b_nn) * 4);
            asm volatile("cp.async.cg.shared.global [%0], [%1], 16;"
                         :: "r"(dst), "l"(src));
        }
    };

    stage(0, 0);
    asm volatile("cp.async.commit_group;");

    for (int t = 0; t < ntiles; t++) {
        const int buf = t & 1;
        asm volatile("cp.async.wait_group 0;");
        __syncthreads();
        if (t + 1 < ntiles) {
            stage(t + 1, buf ^ 1);
            asm volatile("cp.async.commit_group;");
        }

        const float* Ab = As + buf * AELEM;
        const float* Bb_ = Bs + buf * BELEM;
#pragma unroll
        for (int k8 = 0; k8 < GBK; k8 += 8) {
            unsigned a[2][4], b[8][2];
#pragma unroll
            for (int ma = 0; ma < 2; ma++) {
                const int mb = wm + ma * 16 + lr;
                a[ma][0] = tf32u(Ab[(mb    ) * ASTR + k8 + lc    ]);
                a[ma][1] = tf32u(Ab[(mb + 8) * ASTR + k8 + lc    ]);
                a[ma][2] = tf32u(Ab[(mb    ) * ASTR + k8 + lc + 4]);
                a[ma][3] = tf32u(Ab[(mb + 8) * ASTR + k8 + lc + 4]);
            }
#pragma unroll
            for (int na = 0; na < 8; na++) {
                const int nb = wn + na * 8 + lr;
                b[na][0] = tf32u(Bb_[(k8 + lc    ) * BSTR + nb]);
                b[na][1] = tf32u(Bb_[(k8 + lc + 4) * BSTR + nb]);
            }
#pragma unroll
            for (int ma = 0; ma < 2; ma++)
#pragma unroll
                for (int na = 0; na < 8; na++)
                    mma_tf32(acc[ma][na], a[ma], b[na]);
        }
        __syncthreads();
    }

    // ---- epilogue: c0,c1 at (row, col..col+1); c2,c3 at (row+8, ..) ----
#pragma unroll
    for (int ma = 0; ma < 2; ma++) {
#pragma unroll
        for (int h = 0; h < 2; h++) {
            const int row = bm + wm + ma * 16 + lr + 8 * h;
            if (row >= M) continue;
#pragma unroll
            for (int na = 0; na < 8; na++) {
                const int col = bn + wn + na * 8 + lc * 2;
                float vx = acc[ma][na][2 * h + 0];
                float vy = acc[ma][na][2 * h + 1];
                if (flags & 1) {
                    const float2 bb = *(const float2*)&bias[col];
                    vx += bb.x; vy += bb.y;
                }
                if (flags & 2) { vx = gelu_f(vx); vy = gelu_f(vy); }
                if (flags & 4) {
                    const float2 rr = *(const float2*)&R[(size_t)row * N + col];
                    vx += rr.x; vy += rr.y;
                }
                float2 o; o.x = vx; o.y = vy;
                *(float2*)&C[(size_t)row * N + col] = o;
            }
        }
    }
}

// ---------------------------------------------------------------------------
// LayerNorm (row length Dd=1024). out row stride parameterized so the speaker
// row can write directly into g_cond.
// ---------------------------------------------------------------------------
__global__ __launch_bounds__(256) void ln_kernel(
    const float* __restrict__ in, float* __restrict__ out,
    const float* __restrict__ g, const float* __restrict__ b, int out_stride)
{
    const int row = blockIdx.x;
    const float* x = in + (size_t)row * Dd;
    float* y = out + (size_t)row * out_stride;
    const int t = threadIdx.x;

    float v[4];
    float s = 0.f, sq = 0.f;
#pragma unroll
    for (int i = 0; i < 4; i++) {
        float a = x[t + 256 * i];
        v[i] = a; s += a; sq += a * a;
    }
#pragma unroll
    for (int o = 16; o > 0; o >>= 1) {
        s  += __shfl_xor_sync(0xffffffffu, s,  o);
        sq += __shfl_xor_sync(0xffffffffu, sq, o);
    }
    __shared__ float ss[8], sqs[8];
    if ((t & 31) == 0) { ss[t >> 5] = s; sqs[t >> 5] = sq; }
    __syncthreads();
    if (t < 32) {
        float ts = (t < 8) ? ss[t]  : 0.f;
        float tq = (t < 8) ? sqs[t] : 0.f;
#pragma unroll
        for (int o = 4; o > 0; o >>= 1) {
            ts += __shfl_xor_sync(0xffffffffu, ts, o);
            tq += __shfl_xor_sync(0xffffffffu, tq, o);
        }
        if (t == 0) { ss[0] = ts; sqs[0] = tq; }
    }
    __syncthreads();
    const float mean = ss[0] * (1.0f / Dd);
    const float var  = sqs[0] * (1.0f / Dd) - mean * mean;
    const float rstd = rsqrtf(var + 1e-5f);
#pragma unroll
    for (int i = 0; i < 4; i++) {
        const int idx = t + 256 * i;
        y[idx] = (v[i] - mean) * rstd * g[idx] + b[idx];
    }
}

// ---------------------------------------------------------------------------
// Embedding gathers
// ---------------------------------------------------------------------------
__global__ void embed_audio_kernel(const int* __restrict__ tok,
                                   const float* __restrict__ w)
{
    const int row = blockIdx.x;               // 0..NT-1
    const int t = tok[row];
    const float4* src = (const float4*)(w + (size_t)t * Dd);
    float4* dst = (float4*)(g_x + (size_t)row * Dd);
    dst[threadIdx.x] = src[threadIdx.x];      // 256 threads x float4
}

__global__ void embed_text_kernel(const int* __restrict__ tok,
                                  const float* __restrict__ w)
{
    const int b = blockIdx.y, t = blockIdx.x;
    const int tk = tok[b * Tt + t];
    const float4* src = (const float4*)(w + (size_t)tk * Dd);
    float4* dst = (float4*)(g_cond + ((size_t)(b * Cc + 1 + t)) * Dd);
    dst[threadIdx.x] = src[threadIdx.x];
}

// ---------------------------------------------------------------------------
// RoPE in-place on q and k inside g_qkv. Block per token, 512 threads
// (16 heads x 32 rotary pairs).
// ---------------------------------------------------------------------------
__global__ void rope_kernel()
{
    const int row = blockIdx.x;               // b*S + s
    const int s = row & (Ss - 1);
    const int h = threadIdx.x >> 5;
    const int j = threadIdx.x & 31;
    const float inv = exp2f(-0.415241011860920f * (float)j);
    const float ang = (float)s * inv;
    float sn, cs;
    sincosf(ang, &sn, &cs);

    float* q = g_qkv + (size_t)row * (3 * Dd) + h * HDd;
    float x1 = q[j], x2 = q[j + 32];
    q[j]      = x1 * cs - x2 * sn;
    q[j + 32] = x2 * cs + x1 * sn;

    float* k = q + Dd;
    x1 = k[j]; x2 = k[j + 32];
    k[j]      = x1 * cs - x2 * sn;
    k[j + 32] = x2 * cs + x1 * sn;
}

// ---------------------------------------------------------------------------
// Flash-style attention. One block = (q-tile of 64 rows, head, batch);
// 64 threads, each owns one q row fully in registers.
// ---------------------------------------------------------------------------
template<bool CAUSAL>
__global__ __launch_bounds__(64) void attn_kernel(
    const float* __restrict__ Qp, const float* __restrict__ Kp,
    const float* __restrict__ Vp, float* __restrict__ Op,
    int kv_rows, int q_rstride, int kv_rstride,
    long q_bstride, long kv_bstride)
{
    const int b   = blockIdx.z;
    const int h   = blockIdx.y;
    const int qt0 = blockIdx.x * 64;
    const int tid = threadIdx.x;
    const int qi  = qt0 + tid;

    __shared__ float Ks[64][68];
    __shared__ float Vs[64][68];

    const float* qrow = Qp + (size_t)b * q_bstride + (size_t)qi * q_rstride + h * HDd;
    float4 q4[16];
#pragma unroll
    for (int d = 0; d < 16; d++) q4[d] = *(const float4*)(qrow + 4 * d);

    float4 o4[16];
#pragma unroll
    for (int d = 0; d < 16; d++) o4[d] = make_float4(0.f, 0.f, 0.f, 0.f);
    float m = -1e30f, l = 0.f;

    const int kv_limit = CAUSAL ? min(kv_rows, qt0 + 64) : kv_rows;

    for (int j0 = 0; j0 < kv_limit; j0 += 64) {
        __syncthreads();
        const int jr = j0 + tid;
        const bool valid = jr < kv_rows;
        const float* kr = Kp + (size_t)b * kv_bstride + (size_t)jr * kv_rstride + h * HDd;
        const float* vr = Vp + (size_t)b * kv_bstride + (size_t)jr * kv_rstride + h * HDd;
#pragma unroll
        for (int d = 0; d < 16; d++) {
            float4 kk = valid ? *(const float4*)(kr + 4 * d) : make_float4(0.f,0.f,0.f,0.f);
            float4 vv = valid ? *(const float4*)(vr + 4 * d) : make_float4(0.f,0.f,0.f,0.f);
            *(float4*)&Ks[tid][4 * d] = kk;
            *(float4*)&Vs[tid][4 * d] = vv;
        }
        __syncthreads();

        int jmax = min(64, kv_rows - j0);
        if (CAUSAL) jmax = min(jmax, qi - j0 + 1);

        for (int j = 0; j < jmax; j++) {
            const float4* krow4 = (const float4*)&Ks[j][0];
            float s = 0.f;
#pragma unroll
            for (int d = 0; d < 16; d++) {
                float4 kk = krow4[d];
                s += q4[d].x * kk.x + q4[d].y * kk.y + q4[d].z * kk.z + q4[d].w * kk.w;
            }
            s *= 0.125f;  // 1/sqrt(64)
            const float mn   = fmaxf(m, s);
            const float corr = expf(m - mn);
            const float p    = expf(s - mn);
            l = l * corr + p;
            const float4* vrow4 = (const float4*)&Vs[j][0];
#pragma unroll
            for (int d = 0; d < 16; d++) {
                float4 vv = vrow4[d];
                o4[d].x = o4[d].x * corr + p * vv.x;
                o4[d].y = o4[d].y * corr + p * vv.y;
                o4[d].z = o4[d].z * corr + p * vv.z;
                o4[d].w = o4[d].w * corr + p * vv.w;
            }
            m = mn;
        }
    }

    const float invl = 1.0f / l;
    float* orow = Op + ((size_t)(b * Ss + qi)) * Dd + h * HDd;
#pragma unroll
    for (int d = 0; d < 16; d++) {
        float4 v = o4[d];
        v.x *= invl; v.y *= invl; v.z *= invl; v.w *= invl;
        *(float4*)(orow + 4 * d) = v;
    }
}

// ---------------------------------------------------------------------------
// Host orchestration
// ---------------------------------------------------------------------------
extern "C" void kernel_launch(void* const* d_in, const int* in_sizes, int n_in,
                              void* d_out, int out_size)
{
    (void)in_sizes; (void)n_in; (void)out_size;

    const int*   audio  = (const int*)  d_in[0];
    const int*   text   = (const int*)  d_in[1];
    const float* spk_e  = (const float*)d_in[2];
    const float* tok_w  = (const float*)d_in[3];
    const float* text_w = (const float*)d_in[4];
    const float* spk_w  = (const float*)d_in[5];
    const float* spk_b  = (const float*)d_in[6];
    const float* spk_g  = (const float*)d_in[7];
    const float* spk_bb = (const float*)d_in[8];
    const float* n1g    = (const float*)d_in[9];
    const float* n1b    = (const float*)d_in[10];
    const float* qkvw   = (const float*)d_in[11];
    const float* outw   = (const float*)d_in[12];
    const float* outb   = (const float*)d_in[13];
    const float* ncg    = (const float*)d_in[14];
    const float* ncb    = (const float*)d_in[15];
    const float* cqw    = (const float*)d_in[16];
    const float* ckvw   = (const float*)d_in[17];
    const float* coutw  = (const float*)d_in[18];
    const float* coutb  = (const float*)d_in[19];
    const float* n2g    = (const float*)d_in[20];
    const float* n2b    = (const float*)d_in[21];
    const float* f1w    = (const float*)d_in[22];
    const float* f1b    = (const float*)d_in[23];
    const float* f2w    = (const float*)d_in[24];
    const float* f2b    = (const float*)d_in[25];
    const float* nog    = (const float*)d_in[26];
    const float* nob    = (const float*)d_in[27];
    const float* lmw    = (const float*)d_in[28];

    float *px, *ph, *pqkv, *po, *pq, *pf, *pcond, *pckv, *pspk;
    cudaGetSymbolAddress((void**)&px,    g_x);
    cudaGetSymbolAddress((void**)&ph,    g_h);
    cudaGetSymbolAddress((void**)&pqkv,  g_qkv);
    cudaGetSymbolAddress((void**)&po,    g_o);
    cudaGetSymbolAddress((void**)&pq,    g_q);
    cudaGetSymbolAddress((void**)&pf,    g_f);
    cudaGetSymbolAddress((void**)&pcond, g_cond);
    cudaGetSymbolAddress((void**)&pckv,  g_ckv);
    cudaGetSymbolAddress((void**)&pspk,  g_spk);

    // ---- embeddings + conditioning ----
    embed_audio_kernel<<<NT, 256>>>(audio, tok_w);
    gemm_tc<<<dim3(Dd / GBN, 1), 256>>>(spk_e, spk_w, spk_b, nullptr, pspk,
                                        Bb, Dd, 256, /*bias|gelu*/ 3);
    ln_kernel<<<Bb, 256>>>(pspk, pcond, spk_g, spk_bb, Cc * Dd);
    embed_text_kernel<<<dim3(Tt, Bb), 256>>>(text, text_w);

    for (int l = 0; l < Ll; l++) {
        // --- self attention ---
        ln_kernel<<<NT, 256>>>(px, ph, n1g + l * Dd, n1b + l * Dd, Dd);
        gemm_tc<<<dim3(3 * Dd / GBN, NT / GBM), 256>>>(
            ph, qkvw + (size_t)l * Dd * 3 * Dd, nullptr, nullptr, pqkv,
            NT, 3 * Dd, Dd, 0);
        rope_kernel<<<NT, 512>>>();
        attn_kernel<true><<<dim3(Ss / 64, Hh, Bb), 64>>>(
            pqkv, pqkv + Dd, pqkv + 2 * Dd, po,
            Ss, 3 * Dd, 3 * Dd, (long)Ss * 3 * Dd, (long)Ss * 3 * Dd);
        gemm_tc<<<dim3(Dd / GBN, NT / GBM), 256>>>(
            po, outw + (size_t)l * Dd * Dd, outb + l * Dd, px, px,
            NT, Dd, Dd, /*bias|res*/ 5);

        // --- cross attention ---
        ln_kernel<<<NT, 256>>>(px, ph, ncg + l * Dd, ncb + l * Dd, Dd);
        gemm_tc<<<dim3(Dd / GBN, NT / GBM), 256>>>(
            ph, cqw + (size_t)l * Dd * Dd, nullptr, nullptr, pq,
            NT, Dd, Dd, 0);
        gemm_tc<<<dim3(2 * Dd / GBN, (Bb * Cc + GBM - 1) / GBM), 256>>>(
            pcond, ckvw + (size_t)l * Dd * 2 * Dd, nullptr, nullptr, pckv,
            Bb * Cc, 2 * Dd, Dd, 0);
        attn_kernel<false><<<dim3(Ss / 64, Hh, Bb), 64>>>(
            pq, pckv, pckv + Dd, po,
            Cc, Dd, 2 * Dd, (long)Ss * Dd, (long)Cc * 2 * Dd);
        gemm_tc<<<dim3(Dd / GBN, NT / GBM), 256>>>(
            po, coutw + (size_t)l * Dd * Dd, coutb + l * Dd, px, px,
            NT, Dd, Dd, 5);

        // --- FFN ---
        ln_kernel<<<NT, 256>>>(px, ph, n2g + l * Dd, n2b + l * Dd, Dd);
        gemm_tc<<<dim3(4 * Dd / GBN, NT / GBM), 256>>>(
            ph, f1w + (size_t)l * Dd * 4 * Dd, f1b + l * 4 * Dd, nullptr, pf,
            NT, 4 * Dd, Dd, /*bias|gelu*/ 3);
        gemm_tc<<<dim3(Dd / GBN, NT / GBM), 256>>>(
            pf, f2w + (size_t)l * 4 * Dd * Dd, f2b + l * Dd, px, px,
            NT, Dd, 4 * Dd, 5);
    }

    // ---- output head ----
    ln_kernel<<<NT, 256>>>(px, ph, nog, nob, Dd);
    gemm_tc<<<dim3(1024 / GBN, NT / GBM), 256>>>(
        ph, lmw, nullptr, nullptr, (float*)d_out, NT, 1024, Dd, 0);
}

// round 6
// speedup vs baseline: 1.4798x; 1.4798x over previous
#include <cuda_runtime.h>
#include <math.h>

// ---------------------------------------------------------------------------
// Problem constants
// ---------------------------------------------------------------------------
#define Bb   2
#define Ss   1024
#define Tt   128
#define Dd   1024
#define Hh   16
#define HDd  64
#define Ll   6
#define Cc   129            // 1 + T conditioning tokens
#define NT   (Bb*Ss)        // 2048 flattened audio tokens

// ---------------------------------------------------------------------------
// Scratch (device globals; allocation-free per harness rules)
// ---------------------------------------------------------------------------
__device__ float g_x   [NT*Dd];
__device__ float g_h   [NT*Dd];
__device__ float g_qkv [NT*3*Dd];
__device__ float g_o   [NT*Dd];
__device__ float g_q   [NT*Dd];
__device__ float g_f   [NT*4*Dd];
__device__ float g_cond[Bb*Cc*Dd];
__device__ float g_ckv [Bb*Cc*2*Dd];
__device__ float g_spk [Bb*Dd];

__device__ __forceinline__ float gelu_f(float x) {
    return 0.5f * x * (1.0f + erff(x * 0.70710678118654752f));
}

__device__ __forceinline__ float tf32r(float x) {
    unsigned u;
    asm("cvt.rna.tf32.f32 %0, %1;" : "=r"(u) : "f"(x));
    return __int_as_float(u);
}

__device__ __forceinline__ void mma_tf32(float* c, const unsigned* a, const unsigned* b) {
    asm volatile(
        "mma.sync.aligned.m16n8k8.row.col.f32.tf32.tf32.f32 "
        "{%0,%1,%2,%3}, {%4,%5,%6,%7}, {%8,%9}, {%0,%1,%2,%3};"
        : "+f"(c[0]), "+f"(c[1]), "+f"(c[2]), "+f"(c[3])
        : "r"(a[0]), "r"(a[1]), "r"(a[2]), "r"(a[3]),
          "r"(b[0]), "r"(b[1]));
}

// ---------------------------------------------------------------------------
// TF32 tensor-core GEMM (R4 structure + register-level prefetch pipeline).
// C[M,N] = A[M,K] @ B[K,N]  (+bias, +gelu, +residual)
// 128x128 block tile, BK=32, 128 threads (4 warps, 64x64 warp tiles).
// flags: 1 = add bias (len N), 2 = gelu, 4 = add residual R[M,N]
// N % 128 == 0, K % 32 == 0. M arbitrary (guarded).
// Smem strides conflict-free for fragment reads (As 36, Bs 136).
// Pipeline: LDG tile t+1 into registers before the MMA loop of tile t;
// STS+tf32-convert at the top of the next iteration. Arithmetic identical
// to the un-pipelined version (same conversion point, same k-order).
// ---------------------------------------------------------------------------
#define GBM 128
#define GBN 128
#define GBK 32
#define ASTR 36
#define BSTR 136

__global__ __launch_bounds__(128, 2) void gemm_tc(
    const float* __restrict__ A, const float* __restrict__ Bm,
    const float* __restrict__ bias, const float* __restrict__ R,
    float* __restrict__ C, int M, int N, int K, int flags)
{
    __shared__ float As[GBM * ASTR];   // [m][k]
    __shared__ float Bs[GBK * BSTR];   // [k][n]

    const int tid  = threadIdx.x;
    const int lane = tid & 31;
    const int wid  = tid >> 5;
    const int wm   = (wid >> 1) * 64;
    const int wn   = (wid & 1) * 64;
    const int bm   = blockIdx.y * GBM;
    const int bn   = blockIdx.x * GBN;
    const int lr   = lane >> 2;
    const int lc   = lane & 3;

    float acc[4][8][4];
#pragma unroll
    for (int i = 0; i < 4; i++)
#pragma unroll
        for (int j = 0; j < 8; j++)
#pragma unroll
            for (int r = 0; r < 4; r++) acc[i][j][r] = 0.0f;

    // staging coordinates (per j-slice)
    //   A: f4 = tid + 128*j ; r = f4>>3 (0..127) ; kk = (f4&7)*4
    //   B: f4 = tid + 128*j ; kr = f4>>5 (0..31) ; nn = (f4&31)*4
    float4 pa[8], pb[8];

    auto fetch = [&](int k0) {
#pragma unroll
        for (int j = 0; j < 8; j++) {
            const int f4  = tid + 128 * j;
            const int r   = f4 >> 3;
            const int kk  = (f4 & 7) * 4;
            const int row = bm + r;
            pa[j] = (row < M) ? *(const float4*)(A + (size_t)row * K + k0 + kk)
                              : make_float4(0.f, 0.f, 0.f, 0.f);
        }
#pragma unroll
        for (int j = 0; j < 8; j++) {
            const int f4 = tid + 128 * j;
            const int kr = f4 >> 5;
            const int nn = (f4 & 31) * 4;
            pb[j] = *(const float4*)(Bm + (size_t)(k0 + kr) * N + bn + nn);
        }
    };

    const int ntiles = K / GBK;
    fetch(0);

    for (int t = 0; t < ntiles; t++) {
        // ---- store prefetched tile to smem (tf32-rounded) ----
#pragma unroll
        for (int j = 0; j < 8; j++) {
            const int f4 = tid + 128 * j;
            const int r  = f4 >> 3;
            const int kk = (f4 & 7) * 4;
            float* dst = &As[r * ASTR + kk];
            dst[0] = tf32r(pa[j].x); dst[1] = tf32r(pa[j].y);
            dst[2] = tf32r(pa[j].z); dst[3] = tf32r(pa[j].w);
        }
#pragma unroll
        for (int j = 0; j < 8; j++) {
            const int f4 = tid + 128 * j;
            const int kr = f4 >> 5;
            const int nn = (f4 & 31) * 4;
            float* dst = &Bs[kr * BSTR + nn];
            dst[0] = tf32r(pb[j].x); dst[1] = tf32r(pb[j].y);
            dst[2] = tf32r(pb[j].z); dst[3] = tf32r(pb[j].w);
        }
        __syncthreads();

        // ---- prefetch next tile into registers (latency hidden by MMAs) ----
        if (t + 1 < ntiles) fetch((t + 1) * GBK);

        // ---- compute tile t ----
#pragma unroll
        for (int k8 = 0; k8 < GBK; k8 += 8) {
            unsigned a[4][4], b[8][2];
#pragma unroll
            for (int ma = 0; ma < 4; ma++) {
                const int mb = wm + ma * 16 + lr;
                a[ma][0] = __float_as_uint(As[(mb    ) * ASTR + k8 + lc    ]);
                a[ma][1] = __float_as_uint(As[(mb + 8) * ASTR + k8 + lc    ]);
                a[ma][2] = __float_as_uint(As[(mb    ) * ASTR + k8 + lc + 4]);
                a[ma][3] = __float_as_uint(As[(mb + 8) * ASTR + k8 + lc + 4]);
            }
#pragma unroll
            for (int na = 0; na < 8; na++) {
                const int nb = wn + na * 8 + lr;
                b[na][0] = __float_as_uint(Bs[(k8 + lc    ) * BSTR + nb]);
                b[na][1] = __float_as_uint(Bs[(k8 + lc + 4) * BSTR + nb]);
            }
#pragma unroll
            for (int ma = 0; ma < 4; ma++)
#pragma unroll
                for (int na = 0; na < 8; na++)
                    mma_tf32(acc[ma][na], a[ma], b[na]);
        }
        __syncthreads();
    }

    // ---- epilogue: c0,c1 at (row, col..col+1); c2,c3 at (row+8, ..) ----
#pragma unroll
    for (int ma = 0; ma < 4; ma++) {
#pragma unroll
        for (int h = 0; h < 2; h++) {
            const int row = bm + wm + ma * 16 + lr + 8 * h;
            if (row >= M) continue;
#pragma unroll
            for (int na = 0; na < 8; na++) {
                const int col = bn + wn + na * 8 + lc * 2;
                float vx = acc[ma][na][2 * h + 0];
                float vy = acc[ma][na][2 * h + 1];
                if (flags & 1) {
                    const float2 bb = *(const float2*)&bias[col];
                    vx += bb.x; vy += bb.y;
                }
                if (flags & 2) { vx = gelu_f(vx); vy = gelu_f(vy); }
                if (flags & 4) {
                    const float2 rr = *(const float2*)&R[(size_t)row * N + col];
                    vx += rr.x; vy += rr.y;
                }
                float2 o; o.x = vx; o.y = vy;
                *(float2*)&C[(size_t)row * N + col] = o;
            }
        }
    }
}

// ---------------------------------------------------------------------------
// LayerNorm (row length Dd=1024). out row stride parameterized so the speaker
// row can write directly into g_cond.
// ---------------------------------------------------------------------------
__global__ __launch_bounds__(256) void ln_kernel(
    const float* __restrict__ in, float* __restrict__ out,
    const float* __restrict__ g, const float* __restrict__ b, int out_stride)
{
    const int row = blockIdx.x;
    const float* x = in + (size_t)row * Dd;
    float* y = out + (size_t)row * out_stride;
    const int t = threadIdx.x;

    float v[4];
    float s = 0.f, sq = 0.f;
#pragma unroll
    for (int i = 0; i < 4; i++) {
        float a = x[t + 256 * i];
        v[i] = a; s += a; sq += a * a;
    }
#pragma unroll
    for (int o = 16; o > 0; o >>= 1) {
        s  += __shfl_xor_sync(0xffffffffu, s,  o);
        sq += __shfl_xor_sync(0xffffffffu, sq, o);
    }
    __shared__ float ss[8], sqs[8];
    if ((t & 31) == 0) { ss[t >> 5] = s; sqs[t >> 5] = sq; }
    __syncthreads();
    if (t < 32) {
        float ts = (t < 8) ? ss[t]  : 0.f;
        float tq = (t < 8) ? sqs[t] : 0.f;
#pragma unroll
        for (int o = 4; o > 0; o >>= 1) {
            ts += __shfl_xor_sync(0xffffffffu, ts, o);
            tq += __shfl_xor_sync(0xffffffffu, tq, o);
        }
        if (t == 0) { ss[0] = ts; sqs[0] = tq; }
    }
    __syncthreads();
    const float mean = ss[0] * (1.0f / Dd);
    const float var  = sqs[0] * (1.0f / Dd) - mean * mean;
    const float rstd = rsqrtf(var + 1e-5f);
#pragma unroll
    for (int i = 0; i < 4; i++) {
        const int idx = t + 256 * i;
        y[idx] = (v[i] - mean) * rstd * g[idx] + b[idx];
    }
}

// ---------------------------------------------------------------------------
// Embedding gathers
// ---------------------------------------------------------------------------
__global__ void embed_audio_kernel(const int* __restrict__ tok,
                                   const float* __restrict__ w)
{
    const int row = blockIdx.x;               // 0..NT-1
    const int t = tok[row];
    const float4* src = (const float4*)(w + (size_t)t * Dd);
    float4* dst = (float4*)(g_x + (size_t)row * Dd);
    dst[threadIdx.x] = src[threadIdx.x];      // 256 threads x float4
}

__global__ void embed_text_kernel(const int* __restrict__ tok,
                                  const float* __restrict__ w)
{
    const int b = blockIdx.y, t = blockIdx.x;
    const int tk = tok[b * Tt + t];
    const float4* src = (const float4*)(w + (size_t)tk * Dd);
    float4* dst = (float4*)(g_cond + ((size_t)(b * Cc + 1 + t)) * Dd);
    dst[threadIdx.x] = src[threadIdx.x];
}

// ---------------------------------------------------------------------------
// RoPE in-place on q and k inside g_qkv. Block per token, 512 threads
// (16 heads x 32 rotary pairs).
// ---------------------------------------------------------------------------
__global__ void rope_kernel()
{
    const int row = blockIdx.x;               // b*S + s
    const int s = row & (Ss - 1);
    const int h = threadIdx.x >> 5;
    const int j = threadIdx.x & 31;
    const float inv = exp2f(-0.415241011860920f * (float)j);
    const float ang = (float)s * inv;
    float sn, cs;
    sincosf(ang, &sn, &cs);

    float* q = g_qkv + (size_t)row * (3 * Dd) + h * HDd;
    float x1 = q[j], x2 = q[j + 32];
    q[j]      = x1 * cs - x2 * sn;
    q[j + 32] = x2 * cs + x1 * sn;

    float* k = q + Dd;
    x1 = k[j]; x2 = k[j + 32];
    k[j]      = x1 * cs - x2 * sn;
    k[j + 32] = x2 * cs + x1 * sn;
}

// ---------------------------------------------------------------------------
// Flash-style attention. One block = (q-tile of 64 rows, head, batch);
// 64 threads, each owns one q row fully in registers.
// ---------------------------------------------------------------------------
template<bool CAUSAL>
__global__ __launch_bounds__(64) void attn_kernel(
    const float* __restrict__ Qp, const float* __restrict__ Kp,
    const float* __restrict__ Vp, float* __restrict__ Op,
    int kv_rows, int q_rstride, int kv_rstride,
    long q_bstride, long kv_bstride)
{
    const int b   = blockIdx.z;
    const int h   = blockIdx.y;
    const int qt0 = blockIdx.x * 64;
    const int tid = threadIdx.x;
    const int qi  = qt0 + tid;

    __shared__ float Ks[64][68];
    __shared__ float Vs[64][68];

    const float* qrow = Qp + (size_t)b * q_bstride + (size_t)qi * q_rstride + h * HDd;
    float4 q4[16];
#pragma unroll
    for (int d = 0; d < 16; d++) q4[d] = *(const float4*)(qrow + 4 * d);

    float4 o4[16];
#pragma unroll
    for (int d = 0; d < 16; d++) o4[d] = make_float4(0.f, 0.f, 0.f, 0.f);
    float m = -1e30f, l = 0.f;

    const int kv_limit = CAUSAL ? min(kv_rows, qt0 + 64) : kv_rows;

    for (int j0 = 0; j0 < kv_limit; j0 += 64) {
        __syncthreads();
        const int jr = j0 + tid;
        const bool valid = jr < kv_rows;
        const float* kr = Kp + (size_t)b * kv_bstride + (size_t)jr * kv_rstride + h * HDd;
        const float* vr = Vp + (size_t)b * kv_bstride + (size_t)jr * kv_rstride + h * HDd;
#pragma unroll
        for (int d = 0; d < 16; d++) {
            float4 kk = valid ? *(const float4*)(kr + 4 * d) : make_float4(0.f,0.f,0.f,0.f);
            float4 vv = valid ? *(const float4*)(vr + 4 * d) : make_float4(0.f,0.f,0.f,0.f);
            *(float4*)&Ks[tid][4 * d] = kk;
            *(float4*)&Vs[tid][4 * d] = vv;
        }
        __syncthreads();

        int jmax = min(64, kv_rows - j0);
        if (CAUSAL) jmax = min(jmax, qi - j0 + 1);

        for (int j = 0; j < jmax; j++) {
            const float4* krow4 = (const float4*)&Ks[j][0];
            float s = 0.f;
#pragma unroll
            for (int d = 0; d < 16; d++) {
                float4 kk = krow4[d];
                s += q4[d].x * kk.x + q4[d].y * kk.y + q4[d].z * kk.z + q4[d].w * kk.w;
            }
            s *= 0.125f;  // 1/sqrt(64)
            const float mn   = fmaxf(m, s);
            const float corr = expf(m - mn);
            const float p    = expf(s - mn);
            l = l * corr + p;
            const float4* vrow4 = (const float4*)&Vs[j][0];
#pragma unroll
            for (int d = 0; d < 16; d++) {
                float4 vv = vrow4[d];
                o4[d].x = o4[d].x * corr + p * vv.x;
                o4[d].y = o4[d].y * corr + p * vv.y;
                o4[d].z = o4[d].z * corr + p * vv.z;
                o4[d].w = o4[d].w * corr + p * vv.w;
            }
            m = mn;
        }
    }

    const float invl = 1.0f / l;
    float* orow = Op + ((size_t)(b * Ss + qi)) * Dd + h * HDd;
#pragma unroll
    for (int d = 0; d < 16; d++) {
        float4 v = o4[d];
        v.x *= invl; v.y *= invl; v.z *= invl; v.w *= invl;
        *(float4*)(orow + 4 * d) = v;
    }
}

// ---------------------------------------------------------------------------
// Host orchestration
// ---------------------------------------------------------------------------
extern "C" void kernel_launch(void* const* d_in, const int* in_sizes, int n_in,
                              void* d_out, int out_size)
{
    (void)in_sizes; (void)n_in; (void)out_size;

    const int*   audio  = (const int*)  d_in[0];
    const int*   text   = (const int*)  d_in[1];
    const float* spk_e  = (const float*)d_in[2];
    const float* tok_w  = (const float*)d_in[3];
    const float* text_w = (const float*)d_in[4];
    const float* spk_w  = (const float*)d_in[5];
    const float* spk_b  = (const float*)d_in[6];
    const float* spk_g  = (const float*)d_in[7];
    const float* spk_bb = (const float*)d_in[8];
    const float* n1g    = (const float*)d_in[9];
    const float* n1b    = (const float*)d_in[10];
    const float* qkvw   = (const float*)d_in[11];
    const float* outw   = (const float*)d_in[12];
    const float* outb   = (const float*)d_in[13];
    const float* ncg    = (const float*)d_in[14];
    const float* ncb    = (const float*)d_in[15];
    const float* cqw    = (const float*)d_in[16];
    const float* ckvw   = (const float*)d_in[17];
    const float* coutw  = (const float*)d_in[18];
    const float* coutb  = (const float*)d_in[19];
    const float* n2g    = (const float*)d_in[20];
    const float* n2b    = (const float*)d_in[21];
    const float* f1w    = (const float*)d_in[22];
    const float* f1b    = (const float*)d_in[23];
    const float* f2w    = (const float*)d_in[24];
    const float* f2b    = (const float*)d_in[25];
    const float* nog    = (const float*)d_in[26];
    const float* nob    = (const float*)d_in[27];
    const float* lmw    = (const float*)d_in[28];

    float *px, *ph, *pqkv, *po, *pq, *pf, *pcond, *pckv, *pspk;
    cudaGetSymbolAddress((void**)&px,    g_x);
    cudaGetSymbolAddress((void**)&ph,    g_h);
    cudaGetSymbolAddress((void**)&pqkv,  g_qkv);
    cudaGetSymbolAddress((void**)&po,    g_o);
    cudaGetSymbolAddress((void**)&pq,    g_q);
    cudaGetSymbolAddress((void**)&pf,    g_f);
    cudaGetSymbolAddress((void**)&pcond, g_cond);
    cudaGetSymbolAddress((void**)&pckv,  g_ckv);
    cudaGetSymbolAddress((void**)&pspk,  g_spk);

    // ---- embeddings + conditioning ----
    embed_audio_kernel<<<NT, 256>>>(audio, tok_w);
    gemm_tc<<<dim3(Dd / GBN, 1), 128>>>(spk_e, spk_w, spk_b, nullptr, pspk,
                                        Bb, Dd, 256, /*bias|gelu*/ 3);
    ln_kernel<<<Bb, 256>>>(pspk, pcond, spk_g, spk_bb, Cc * Dd);
    embed_text_kernel<<<dim3(Tt, Bb), 256>>>(text, text_w);

    for (int l = 0; l < Ll; l++) {
        // --- self attention ---
        ln_kernel<<<NT, 256>>>(px, ph, n1g + l * Dd, n1b + l * Dd, Dd);
        gemm_tc<<<dim3(3 * Dd / GBN, NT / GBM), 128>>>(
            ph, qkvw + (size_t)l * Dd * 3 * Dd, nullptr, nullptr, pqkv,
            NT, 3 * Dd, Dd, 0);
        rope_kernel<<<NT, 512>>>();
        attn_kernel<true><<<dim3(Ss / 64, Hh, Bb), 64>>>(
            pqkv, pqkv + Dd, pqkv + 2 * Dd, po,
            Ss, 3 * Dd, 3 * Dd, (long)Ss * 3 * Dd, (long)Ss * 3 * Dd);
        gemm_tc<<<dim3(Dd / GBN, NT / GBM), 128>>>(
            po, outw + (size_t)l * Dd * Dd, outb + l * Dd, px, px,
            NT, Dd, Dd, /*bias|res*/ 5);

        // --- cross attention ---
        ln_kernel<<<NT, 256>>>(px, ph, ncg + l * Dd, ncb + l * Dd, Dd);
        gemm_tc<<<dim3(Dd / GBN, NT / GBM), 128>>>(
            ph, cqw + (size_t)l * Dd * Dd, nullptr, nullptr, pq,
            NT, Dd, Dd, 0);
        gemm_tc<<<dim3(2 * Dd / GBN, (Bb * Cc + GBM - 1) / GBM), 128>>>(
            pcond, ckvw + (size_t)l * Dd * 2 * Dd, nullptr, nullptr, pckv,
            Bb * Cc, 2 * Dd, Dd, 0);
        attn_kernel<false><<<dim3(Ss / 64, Hh, Bb), 64>>>(
            pq, pckv, pckv + Dd, po,
            Cc, Dd, 2 * Dd, (long)Ss * Dd, (long)Cc * 2 * Dd);
        gemm_tc<<<dim3(Dd / GBN, NT / GBM), 128>>>(
            po, coutw + (size_t)l * Dd * Dd, coutb + l * Dd, px, px,
            NT, Dd, Dd, 5);

        // --- FFN ---
        ln_kernel<<<NT, 256>>>(px, ph, n2g + l * Dd, n2b + l * Dd, Dd);
        gemm_tc<<<dim3(4 * Dd / GBN, NT / GBM), 128>>>(
            ph, f1w + (size_t)l * Dd * 4 * Dd, f1b + l * 4 * Dd, nullptr, pf,
            NT, 4 * Dd, Dd, /*bias|gelu*/ 3);
        gemm_tc<<<dim3(Dd / GBN, NT / GBM), 128>>>(
            pf, f2w + (size_t)l * 4 * Dd * Dd, f2b + l * Dd, px, px,
            NT, Dd, 4 * Dd, 5);
    }

    // ---- output head ----
    ln_kernel<<<NT, 256>>>(px, ph, nog, nob, Dd);
    gemm_tc<<<dim3(1024 / GBN, NT / GBM), 128>>>(
        ph, lmw, nullptr, nullptr, (float*)d_out, NT, 1024, Dd, 0);
}

// round 7
// speedup vs baseline: 1.6193x; 1.0943x over previous
#include <cuda_runtime.h>
#include <math.h>

// ---------------------------------------------------------------------------
// Problem constants
// ---------------------------------------------------------------------------
#define Bb   2
#define Ss   1024
#define Tt   128
#define Dd   1024
#define Hh   16
#define HDd  64
#define Ll   6
#define Cc   129            // 1 + T conditioning tokens
#define NT   (Bb*Ss)        // 2048 flattened audio tokens

// ---------------------------------------------------------------------------
// Scratch (device globals; allocation-free per harness rules)
// ---------------------------------------------------------------------------
__device__ float g_x   [NT*Dd];
__device__ float g_h   [NT*Dd];
__device__ float g_qkv [NT*3*Dd];
__device__ float g_o   [NT*Dd];
__device__ float g_q   [NT*Dd];
__device__ float g_f   [NT*4*Dd];
__device__ float g_cond[Bb*Cc*Dd];
__device__ float g_ckv [Bb*Cc*2*Dd];
__device__ float g_spk [Bb*Dd];

__device__ __forceinline__ float gelu_f(float x) {
    return 0.5f * x * (1.0f + erff(x * 0.70710678118654752f));
}

__device__ __forceinline__ float tf32r(float x) {
    unsigned u;
    asm("cvt.rna.tf32.f32 %0, %1;" : "=r"(u) : "f"(x));
    return __int_as_float(u);
}

__device__ __forceinline__ void mma_tf32(float* c, const unsigned* a, const unsigned* b) {
    asm volatile(
        "mma.sync.aligned.m16n8k8.row.col.f32.tf32.tf32.f32 "
        "{%0,%1,%2,%3}, {%4,%5,%6,%7}, {%8,%9}, {%0,%1,%2,%3};"
        : "+f"(c[0]), "+f"(c[1]), "+f"(c[2]), "+f"(c[3])
        : "r"(a[0]), "r"(a[1]), "r"(a[2]), "r"(a[3]),
          "r"(b[0]), "r"(b[1]));
}

// ---------------------------------------------------------------------------
// TF32 tensor-core GEMM, smem double-buffered (1 sync/tile) + reg prefetch.
// C[M,N] = A[M,K] @ B[K,N]  (+bias, +gelu, +residual)
// 128x128 block tile, BK=32, 128 threads (4 warps, 64x64 warp tiles).
// flags: 1 = add bias (len N), 2 = gelu, 4 = add residual R[M,N]
// N % 128 == 0, K % 32 == 0. M arbitrary (guarded).
// Smem strides conflict-free for fragment reads (As 36, Bs 136); both give
// 16B-aligned float4 staging stores (144B, 544B row pitches).
// Arithmetic identical to R4/R6 (same cvt point, same k-order) -> same rel_err.
// Dynamic smem: 2*(128*36 + 32*136)*4 = 71680 bytes.
// ---------------------------------------------------------------------------
#define GBM 128
#define GBN 128
#define GBK 32
#define ASTR 36
#define BSTR 136
#define AELEM (GBM * ASTR)     // 4608 floats per A stage
#define BELEM (GBK * BSTR)     // 4352 floats per B stage
#define GEMM_SMEM_BYTES (2 * (AELEM + BELEM) * 4)

__global__ __launch_bounds__(128, 2) void gemm_tc(
    const float* __restrict__ A, const float* __restrict__ Bm,
    const float* __restrict__ bias, const float* __restrict__ R,
    float* __restrict__ C, int M, int N, int K, int flags)
{
    extern __shared__ float smem[];
    float* AsBase = smem;                 // 2 stages of A
    float* BsBase = smem + 2 * AELEM;     // 2 stages of B

    const int tid  = threadIdx.x;
    const int lane = tid & 31;
    const int wid  = tid >> 5;
    const int wm   = (wid >> 1) * 64;
    const int wn   = (wid & 1) * 64;
    const int bm   = blockIdx.y * GBM;
    const int bn   = blockIdx.x * GBN;
    const int lr   = lane >> 2;
    const int lc   = lane & 3;

    float acc[4][8][4];
#pragma unroll
    for (int i = 0; i < 4; i++)
#pragma unroll
        for (int j = 0; j < 8; j++)
#pragma unroll
            for (int r = 0; r < 4; r++) acc[i][j][r] = 0.0f;

    // staging coordinates (per j-slice)
    //   A: f4 = tid + 128*j ; r = f4>>3 (0..127) ; kk = (f4&7)*4
    //   B: f4 = tid + 128*j ; kr = f4>>5 (0..31) ; nn = (f4&31)*4
    float4 pa[8], pb[8];

    auto fetch = [&](int k0) {
#pragma unroll
        for (int j = 0; j < 8; j++) {
            const int f4  = tid + 128 * j;
            const int r   = f4 >> 3;
            const int kk  = (f4 & 7) * 4;
            const int row = bm + r;
            pa[j] = (row < M) ? *(const float4*)(A + (size_t)row * K + k0 + kk)
                              : make_float4(0.f, 0.f, 0.f, 0.f);
        }
#pragma unroll
        for (int j = 0; j < 8; j++) {
            const int f4 = tid + 128 * j;
            const int kr = f4 >> 5;
            const int nn = (f4 & 31) * 4;
            pb[j] = *(const float4*)(Bm + (size_t)(k0 + kr) * N + bn + nn);
        }
    };

    // store prefetched regs to smem stage (tf32-rounded), float4 STS
    auto sts = [&](int buf) {
        float* Asb = AsBase + buf * AELEM;
        float* Bsb = BsBase + buf * BELEM;
#pragma unroll
        for (int j = 0; j < 8; j++) {
            const int f4 = tid + 128 * j;
            const int r  = f4 >> 3;
            const int kk = (f4 & 7) * 4;
            float4 v;
            v.x = tf32r(pa[j].x); v.y = tf32r(pa[j].y);
            v.z = tf32r(pa[j].z); v.w = tf32r(pa[j].w);
            *(float4*)&Asb[r * ASTR + kk] = v;
        }
#pragma unroll
        for (int j = 0; j < 8; j++) {
            const int f4 = tid + 128 * j;
            const int kr = f4 >> 5;
            const int nn = (f4 & 31) * 4;
            float4 v;
            v.x = tf32r(pb[j].x); v.y = tf32r(pb[j].y);
            v.z = tf32r(pb[j].z); v.w = tf32r(pb[j].w);
            *(float4*)&Bsb[kr * BSTR + nn] = v;
        }
    };

    const int ntiles = K / GBK;
    fetch(0);
    sts(0);
    __syncthreads();

    for (int t = 0; t < ntiles; t++) {
        // prefetch next tile into registers (hidden by the MMA loop below)
        if (t + 1 < ntiles) fetch((t + 1) * GBK);

        const float* Ab  = AsBase + (t & 1) * AELEM;
        const float* Bb_ = BsBase + (t & 1) * BELEM;
#pragma unroll
        for (int k8 = 0; k8 < GBK; k8 += 8) {
            unsigned a[4][4], b[8][2];
#pragma unroll
            for (int ma = 0; ma < 4; ma++) {
                const int mb = wm + ma * 16 + lr;
                a[ma][0] = __float_as_uint(Ab[(mb    ) * ASTR + k8 + lc    ]);
                a[ma][1] = __float_as_uint(Ab[(mb + 8) * ASTR + k8 + lc    ]);
                a[ma][2] = __float_as_uint(Ab[(mb    ) * ASTR + k8 + lc + 4]);
                a[ma][3] = __float_as_uint(Ab[(mb + 8) * ASTR + k8 + lc + 4]);
            }
#pragma unroll
            for (int na = 0; na < 8; na++) {
                const int nb = wn + na * 8 + lr;
                b[na][0] = __float_as_uint(Bb_[(k8 + lc    ) * BSTR + nb]);
                b[na][1] = __float_as_uint(Bb_[(k8 + lc + 4) * BSTR + nb]);
            }
#pragma unroll
            for (int ma = 0; ma < 4; ma++)
#pragma unroll
                for (int na = 0; na < 8; na++)
                    mma_tf32(acc[ma][na], a[ma], b[na]);
        }

        // stage tile t+1 into the other buffer. Safe: that buffer's readers
        // (tile t-1's compute) were fenced by the previous __syncthreads.
        if (t + 1 < ntiles) sts((t + 1) & 1);
        __syncthreads();
    }

    // ---- epilogue: c0,c1 at (row, col..col+1); c2,c3 at (row+8, ..) ----
#pragma unroll
    for (int ma = 0; ma < 4; ma++) {
#pragma unroll
        for (int h = 0; h < 2; h++) {
            const int row = bm + wm + ma * 16 + lr + 8 * h;
            if (row >= M) continue;
#pragma unroll
            for (int na = 0; na < 8; na++) {
                const int col = bn + wn + na * 8 + lc * 2;
                float vx = acc[ma][na][2 * h + 0];
                float vy = acc[ma][na][2 * h + 1];
                if (flags & 1) {
                    const float2 bb = *(const float2*)&bias[col];
                    vx += bb.x; vy += bb.y;
                }
                if (flags & 2) { vx = gelu_f(vx); vy = gelu_f(vy); }
                if (flags & 4) {
                    const float2 rr = *(const float2*)&R[(size_t)row * N + col];
                    vx += rr.x; vy += rr.y;
                }
                float2 o; o.x = vx; o.y = vy;
                *(float2*)&C[(size_t)row * N + col] = o;
            }
        }
    }
}

// ---------------------------------------------------------------------------
// LayerNorm (row length Dd=1024). out row stride parameterized so the speaker
// row can write directly into g_cond.
// ---------------------------------------------------------------------------
__global__ __launch_bounds__(256) void ln_kernel(
    const float* __restrict__ in, float* __restrict__ out,
    const float* __restrict__ g, const float* __restrict__ b, int out_stride)
{
    const int row = blockIdx.x;
    const float* x = in + (size_t)row * Dd;
    float* y = out + (size_t)row * out_stride;
    const int t = threadIdx.x;

    float v[4];
    float s = 0.f, sq = 0.f;
#pragma unroll
    for (int i = 0; i < 4; i++) {
        float a = x[t + 256 * i];
        v[i] = a; s += a; sq += a * a;
    }
#pragma unroll
    for (int o = 16; o > 0; o >>= 1) {
        s  += __shfl_xor_sync(0xffffffffu, s,  o);
        sq += __shfl_xor_sync(0xffffffffu, sq, o);
    }
    __shared__ float ss[8], sqs[8];
    if ((t & 31) == 0) { ss[t >> 5] = s; sqs[t >> 5] = sq; }
    __syncthreads();
    if (t < 32) {
        float ts = (t < 8) ? ss[t]  : 0.f;
        float tq = (t < 8) ? sqs[t] : 0.f;
#pragma unroll
        for (int o = 4; o > 0; o >>= 1) {
            ts += __shfl_xor_sync(0xffffffffu, ts, o);
            tq += __shfl_xor_sync(0xffffffffu, tq, o);
        }
        if (t == 0) { ss[0] = ts; sqs[0] = tq; }
    }
    __syncthreads();
    const float mean = ss[0] * (1.0f / Dd);
    const float var  = sqs[0] * (1.0f / Dd) - mean * mean;
    const float rstd = rsqrtf(var + 1e-5f);
#pragma unroll
    for (int i = 0; i < 4; i++) {
        const int idx = t + 256 * i;
        y[idx] = (v[i] - mean) * rstd * g[idx] + b[idx];
    }
}

// ---------------------------------------------------------------------------
// Embedding gathers
// ---------------------------------------------------------------------------
__global__ void embed_audio_kernel(const int* __restrict__ tok,
                                   const float* __restrict__ w)
{
    const int row = blockIdx.x;               // 0..NT-1
    const int t = tok[row];
    const float4* src = (const float4*)(w + (size_t)t * Dd);
    float4* dst = (float4*)(g_x + (size_t)row * Dd);
    dst[threadIdx.x] = src[threadIdx.x];      // 256 threads x float4
}

__global__ void embed_text_kernel(const int* __restrict__ tok,
                                  const float* __restrict__ w)
{
    const int b = blockIdx.y, t = blockIdx.x;
    const int tk = tok[b * Tt + t];
    const float4* src = (const float4*)(w + (size_t)tk * Dd);
    float4* dst = (float4*)(g_cond + ((size_t)(b * Cc + 1 + t)) * Dd);
    dst[threadIdx.x] = src[threadIdx.x];
}

// ---------------------------------------------------------------------------
// RoPE in-place on q and k inside g_qkv. Block per token, 512 threads
// (16 heads x 32 rotary pairs).
// ---------------------------------------------------------------------------
__global__ void rope_kernel()
{
    const int row = blockIdx.x;               // b*S + s
    const int s = row & (Ss - 1);
    const int h = threadIdx.x >> 5;
    const int j = threadIdx.x & 31;
    const float inv = exp2f(-0.415241011860920f * (float)j);
    const float ang = (float)s * inv;
    float sn, cs;
    sincosf(ang, &sn, &cs);

    float* q = g_qkv + (size_t)row * (3 * Dd) + h * HDd;
    float x1 = q[j], x2 = q[j + 32];
    q[j]      = x1 * cs - x2 * sn;
    q[j + 32] = x2 * cs + x1 * sn;

    float* k = q + Dd;
    x1 = k[j]; x2 = k[j + 32];
    k[j]      = x1 * cs - x2 * sn;
    k[j + 32] = x2 * cs + x1 * sn;
}

// ---------------------------------------------------------------------------
// Flash-style attention. One block = (q-tile of 64 rows, head, batch);
// 64 threads, each owns one q row fully in registers.
// ---------------------------------------------------------------------------
template<bool CAUSAL>
__global__ __launch_bounds__(64) void attn_kernel(
    const float* __restrict__ Qp, const float* __restrict__ Kp,
    const float* __restrict__ Vp, float* __restrict__ Op,
    int kv_rows, int q_rstride, int kv_rstride,
    long q_bstride, long kv_bstride)
{
    const int b   = blockIdx.z;
    const int h   = blockIdx.y;
    const int qt0 = blockIdx.x * 64;
    const int tid = threadIdx.x;
    const int qi  = qt0 + tid;

    __shared__ float Ks[64][68];
    __shared__ float Vs[64][68];

    const float* qrow = Qp + (size_t)b * q_bstride + (size_t)qi * q_rstride + h * HDd;
    float4 q4[16];
#pragma unroll
    for (int d = 0; d < 16; d++) q4[d] = *(const float4*)(qrow + 4 * d);

    float4 o4[16];
#pragma unroll
    for (int d = 0; d < 16; d++) o4[d] = make_float4(0.f, 0.f, 0.f, 0.f);
    float m = -1e30f, l = 0.f;

    const int kv_limit = CAUSAL ? min(kv_rows, qt0 + 64) : kv_rows;

    for (int j0 = 0; j0 < kv_limit; j0 += 64) {
        __syncthreads();
        const int jr = j0 + tid;
        const bool valid = jr < kv_rows;
        const float* kr = Kp + (size_t)b * kv_bstride + (size_t)jr * kv_rstride + h * HDd;
        const float* vr = Vp + (size_t)b * kv_bstride + (size_t)jr * kv_rstride + h * HDd;
#pragma unroll
        for (int d = 0; d < 16; d++) {
            float4 kk = valid ? *(const float4*)(kr + 4 * d) : make_float4(0.f,0.f,0.f,0.f);
            float4 vv = valid ? *(const float4*)(vr + 4 * d) : make_float4(0.f,0.f,0.f,0.f);
            *(float4*)&Ks[tid][4 * d] = kk;
            *(float4*)&Vs[tid][4 * d] = vv;
        }
        __syncthreads();

        int jmax = min(64, kv_rows - j0);
        if (CAUSAL) jmax = min(jmax, qi - j0 + 1);

        for (int j = 0; j < jmax; j++) {
            const float4* krow4 = (const float4*)&Ks[j][0];
            float s = 0.f;
#pragma unroll
            for (int d = 0; d < 16; d++) {
                float4 kk = krow4[d];
                s += q4[d].x * kk.x + q4[d].y * kk.y + q4[d].z * kk.z + q4[d].w * kk.w;
            }
            s *= 0.125f;  // 1/sqrt(64)
            const float mn   = fmaxf(m, s);
            const float corr = expf(m - mn);
            const float p    = expf(s - mn);
            l = l * corr + p;
            const float4* vrow4 = (const float4*)&Vs[j][0];
#pragma unroll
            for (int d = 0; d < 16; d++) {
                float4 vv = vrow4[d];
                o4[d].x = o4[d].x * corr + p * vv.x;
                o4[d].y = o4[d].y * corr + p * vv.y;
                o4[d].z = o4[d].z * corr + p * vv.z;
                o4[d].w = o4[d].w * corr + p * vv.w;
            }
            m = mn;
        }
    }

    const float invl = 1.0f / l;
    float* orow = Op + ((size_t)(b * Ss + qi)) * Dd + h * HDd;
#pragma unroll
    for (int d = 0; d < 16; d++) {
        float4 v = o4[d];
        v.x *= invl; v.y *= invl; v.z *= invl; v.w *= invl;
        *(float4*)(orow + 4 * d) = v;
    }
}

// ---------------------------------------------------------------------------
// Host orchestration
// ---------------------------------------------------------------------------
extern "C" void kernel_launch(void* const* d_in, const int* in_sizes, int n_in,
                              void* d_out, int out_size)
{
    (void)in_sizes; (void)n_in; (void)out_size;

    const int*   audio  = (const int*)  d_in[0];
    const int*   text   = (const int*)  d_in[1];
    const float* spk_e  = (const float*)d_in[2];
    const float* tok_w  = (const float*)d_in[3];
    const float* text_w = (const float*)d_in[4];
    const float* spk_w  = (const float*)d_in[5];
    const float* spk_b  = (const float*)d_in[6];
    const float* spk_g  = (const float*)d_in[7];
    const float* spk_bb = (const float*)d_in[8];
    const float* n1g    = (const float*)d_in[9];
    const float* n1b    = (const float*)d_in[10];
    const float* qkvw   = (const float*)d_in[11];
    const float* outw   = (const float*)d_in[12];
    const float* outb   = (const float*)d_in[13];
    const float* ncg    = (const float*)d_in[14];
    const float* ncb    = (const float*)d_in[15];
    const float* cqw    = (const float*)d_in[16];
    const float* ckvw   = (const float*)d_in[17];
    const float* coutw  = (const float*)d_in[18];
    const float* coutb  = (const float*)d_in[19];
    const float* n2g    = (const float*)d_in[20];
    const float* n2b    = (const float*)d_in[21];
    const float* f1w    = (const float*)d_in[22];
    const float* f1b    = (const float*)d_in[23];
    const float* f2w    = (const float*)d_in[24];
    const float* f2b    = (const float*)d_in[25];
    const float* nog    = (const float*)d_in[26];
    const float* nob    = (const float*)d_in[27];
    const float* lmw    = (const float*)d_in[28];

    float *px, *ph, *pqkv, *po, *pq, *pf, *pcond, *pckv, *pspk;
    cudaGetSymbolAddress((void**)&px,    g_x);
    cudaGetSymbolAddress((void**)&ph,    g_h);
    cudaGetSymbolAddress((void**)&pqkv,  g_qkv);
    cudaGetSymbolAddress((void**)&po,    g_o);
    cudaGetSymbolAddress((void**)&pq,    g_q);
    cudaGetSymbolAddress((void**)&pf,    g_f);
    cudaGetSymbolAddress((void**)&pcond, g_cond);
    cudaGetSymbolAddress((void**)&pckv,  g_ckv);
    cudaGetSymbolAddress((void**)&pspk,  g_spk);

    // opt-in to >48KB dynamic smem for the GEMM (host attribute; capture-safe)
    cudaFuncSetAttribute(gemm_tc, cudaFuncAttributeMaxDynamicSharedMemorySize,
                         GEMM_SMEM_BYTES);

    const int SB = GEMM_SMEM_BYTES;

    // ---- embeddings + conditioning ----
    embed_audio_kernel<<<NT, 256>>>(audio, tok_w);
    gemm_tc<<<dim3(Dd / GBN, 1), 128, SB>>>(spk_e, spk_w, spk_b, nullptr, pspk,
                                            Bb, Dd, 256, /*bias|gelu*/ 3);
    ln_kernel<<<Bb, 256>>>(pspk, pcond, spk_g, spk_bb, Cc * Dd);
    embed_text_kernel<<<dim3(Tt, Bb), 256>>>(text, text_w);

    for (int l = 0; l < Ll; l++) {
        // --- self attention ---
        ln_kernel<<<NT, 256>>>(px, ph, n1g + l * Dd, n1b + l * Dd, Dd);
        gemm_tc<<<dim3(3 * Dd / GBN, NT / GBM), 128, SB>>>(
            ph, qkvw + (size_t)l * Dd * 3 * Dd, nullptr, nullptr, pqkv,
            NT, 3 * Dd, Dd, 0);
        rope_kernel<<<NT, 512>>>();
        attn_kernel<true><<<dim3(Ss / 64, Hh, Bb), 64>>>(
            pqkv, pqkv + Dd, pqkv + 2 * Dd, po,
            Ss, 3 * Dd, 3 * Dd, (long)Ss * 3 * Dd, (long)Ss * 3 * Dd);
        gemm_tc<<<dim3(Dd / GBN, NT / GBM), 128, SB>>>(
            po, outw + (size_t)l * Dd * Dd, outb + l * Dd, px, px,
            NT, Dd, Dd, /*bias|res*/ 5);

        // --- cross attention ---
        ln_kernel<<<NT, 256>>>(px, ph, ncg + l * Dd, ncb + l * Dd, Dd);
        gemm_tc<<<dim3(Dd / GBN, NT / GBM), 128, SB>>>(
            ph, cqw + (size_t)l * Dd * Dd, nullptr, nullptr, pq,
            NT, Dd, Dd, 0);
        gemm_tc<<<dim3(2 * Dd / GBN, (Bb * Cc + GBM - 1) / GBM), 128, SB>>>(
            pcond, ckvw + (size_t)l * Dd * 2 * Dd, nullptr, nullptr, pckv,
            Bb * Cc, 2 * Dd, Dd, 0);
        attn_kernel<false><<<dim3(Ss / 64, Hh, Bb), 64>>>(
            pq, pckv, pckv + Dd, po,
            Cc, Dd, 2 * Dd, (long)Ss * Dd, (long)Cc * 2 * Dd);
        gemm_tc<<<dim3(Dd / GBN, NT / GBM), 128, SB>>>(
            po, coutw + (size_t)l * Dd * Dd, coutb + l * Dd, px, px,
            NT, Dd, Dd, 5);

        // --- FFN ---
        ln_kernel<<<NT, 256>>>(px, ph, n2g + l * Dd, n2b + l * Dd, Dd);
        gemm_tc<<<dim3(4 * Dd / GBN, NT / GBM), 128, SB>>>(
            ph, f1w + (size_t)l * Dd * 4 * Dd, f1b + l * 4 * Dd, nullptr, pf,
            NT, 4 * Dd, Dd, /*bias|gelu*/ 3);
        gemm_tc<<<dim3(Dd / GBN, NT / GBM), 128, SB>>>(
            pf, f2w + (size_t)l * 4 * Dd * Dd, f2b + l * Dd, px, px,
            NT, Dd, 4 * Dd, 5);
    }

    // ---- output head ----
    ln_kernel<<<NT, 256>>>(px, ph, nog, nob, Dd);
    gemm_tc<<<dim3(1024 / GBN, NT / GBM), 128, SB>>>(
        ph, lmw, nullptr, nullptr, (float*)d_out, NT, 1024, Dd, 0);
}